// round 5
// baseline (speedup 1.0000x reference)
#include <cuda_runtime.h>

#define TT 2048
#define BB 32
#define HH 512

// Scratch (allocation-free: __device__ globals)
__device__ uint2 g_fire[TT];       // (t, bits(dist_completion)) per batch-0 fire
__device__ int   g_nF;             // number of fires, batch 0
__device__ int   g_lastFire[BB];   // last fire index per batch (-1 if none)
__device__ float g_lastDist[BB];   // dist_completion at that fire

// Carry reconstruction: x-1 exact for x in [1,2) (Sterbenz)
__device__ __forceinline__ float integ_after(float x) {
    return (x >= 1.0f) ? (x - 1.0f) : x;
}

// ---------------------------------------------------------------------------
// Kernel 1: single-warp scan, lane = batch. Bit-exact f32 sequential.
// Carried chain: FADD(x=integ+a) -> FSET(sub=[x>=1]) -> FADD(integ=x-sub)
// = 3 fixed-lat-4 fma-pipe ops = 12 cyc/step, NO predicates on the chain
// (FSETP->consumer is scheduled with guard-class ~13-cyc stalls by ptxas).
// lastFire tracking is predicate-free via monotone fmax; lastIntegPre keeps
// one off-chain SEL. Lane 0 records x_t to shared unconditionally; other
// lanes write a dummy slot (same-address collapse). Fire compaction happens
// once at the end via ballot.
// ---------------------------------------------------------------------------
__global__ void k_scan(const float* __restrict__ alphas,
                       const float* __restrict__ integrate,
                       float* __restrict__ out_integ) {
    __shared__ float s_x[TT];
    __shared__ float s_dummy[TT + 2];
    int lane = threadIdx.x;
    const float4* A = (const float4*)(alphas + lane * TT);  // lane's batch row
    float integ0 = integrate[lane];
    float integ  = integ0;
    float lff = 0.0f;                     // (lastFire+1) as float, via fmax
    float lip = 0.0f;                     // integ (pre-add) at last fire
    float* sp = (lane == 0) ? s_x : (s_dummy + 1);

    float4 buf[8], nxt[8];
#pragma unroll
    for (int j = 0; j < 8; j++) buf[j] = A[j];

#define GETA(B, u) ((u & 3) == 0 ? B[(u) >> 2].x : \
                    (u & 3) == 1 ? B[(u) >> 2].y : \
                    (u & 3) == 2 ? B[(u) >> 2].z : B[(u) >> 2].w)

#define BODY32(B, TBASE) do {                                        \
    float* spt = sp + (TBASE);                                       \
    _Pragma("unroll")                                                \
    for (int u = 0; u < 32; u++) {                                   \
        float a = GETA(B, u);                                        \
        float x = integ + a;          /* FADD: fl(integ+alpha)    */ \
        float sub;                    /* FSET: 1.0f if fire       */ \
        asm("set.ge.f32.f32 %0, %1, %2;" : "=f"(sub) : "f"(x), "f"(1.0f)); \
        spt[u] = x;                   /* STS [R+imm], branchless  */ \
        lff = fmaxf(lff, sub * (float)((TBASE) + u + 1));            \
        lip = (sub != 0.0f) ? integ : lip;   /* off-chain SEL     */ \
        integ = x - sub;              /* FADD: exact either way   */ \
    } } while (0)

    for (int b2 = 0; b2 < TT / 64; b2++) {
#pragma unroll
        for (int j = 0; j < 8; j++) nxt[j] = A[b2 * 16 + 8 + j];
        BODY32(buf, b2 * 64);
        if (b2 + 1 < TT / 64) {
#pragma unroll
            for (int j = 0; j < 8; j++) buf[j] = A[(b2 + 1) * 16 + j];
        }
        BODY32(nxt, b2 * 64 + 32);
    }

    g_lastFire[lane] = (int)lff - 1;
    g_lastDist[lane] = 1.0f - lip;      // same bits as in-scan 1-integ at fire
    out_integ[lane]  = integ;           // integrate_new output

    __syncwarp();
    // Ballot-based compaction of batch-0 fires (64 iterations)
    float i0 = __shfl_sync(0xffffffffu, integ0, 0);
    int cnt = 0;
    for (int base = 0; base < TT; base += 32) {
        float x = s_x[base + lane];
        bool  f = (x >= 1.0f);
        unsigned m = __ballot_sync(0xffffffffu, f);
        if (f) {
            int pos = cnt + __popc(m & ((1u << lane) - 1u));
            float xprev = (base + lane == 0) ? i0 : integ_after(s_x[base + lane - 1]);
            float dist  = 1.0f - xprev;           // dist_completion at this fire
            g_fire[pos] = make_uint2((unsigned)(base + lane), __float_as_uint(dist));
        }
        cnt += __popc(m);
    }
    if (lane == 0) g_nF = cnt;
}

// ---------------------------------------------------------------------------
// Kernel 2: blocks 0..2047 -> frame_sel rows; blocks 2048..2079 -> frame_new.
// 128 threads, float4 over H=512. Segment sums are ~2 steps each.
// ---------------------------------------------------------------------------
__global__ void k_frames(const float* __restrict__ hidden,
                         const float* __restrict__ alphas,
                         const float* __restrict__ integrate,
                         const float* __restrict__ frame,
                         float* __restrict__ out) {
    int i   = blockIdx.x;
    int tid = threadIdx.x;  // 0..127

    if (i < TT) {
        const float4* H0 = (const float4*)hidden;  // batch 0: [t][128]
        float4* orow = (float4*)out + (size_t)i * 128 + tid;
        int nF = g_nF;

        if (i >= nF) {
            // fill rows replicate frames[0][0] = frame_init + cur_0 * h_0
            float cur0;
            if (nF > 0 && g_fire[0].x == 0u)
                cur0 = __uint_as_float(g_fire[0].y);   // fired at t=0: dist
            else
                cur0 = alphas[0];                      // no fire at t=0: alpha
            float4 h = H0[tid];
            float4 f = ((const float4*)frame)[tid];
            float4 r;
            r.x = f.x + cur0 * h.x; r.y = f.y + cur0 * h.y;
            r.z = f.z + cur0 * h.z; r.w = f.w + cur0 * h.w;
            *orow = r;
        } else {
            uint2 fe = g_fire[i];
            int   tE = (int)fe.x;
            float wE = __uint_as_float(fe.y);          // cur at closing fire
            float4 acc;
            int tstart;
            if (i == 0) {
                acc = ((const float4*)frame)[tid];     // initial frame carried in
                tstart = 0;
            } else {
                // lead term from previous fire: rem_{tp} * h_{tp}
                uint2 fp = g_fire[i - 1];
                int   tp = (int)fp.x;
                float cur_p = __uint_as_float(fp.y);
                float rem = alphas[tp] - cur_p;        // bitwise same as scan's rem
                float4 h = H0[(size_t)tp * 128 + tid];
                acc.x = rem * h.x; acc.y = rem * h.y;
                acc.z = rem * h.z; acc.w = rem * h.w;
                tstart = tp + 1;
            }
            // interior steps (non-fire): cur = alpha
            for (int t = tstart; t < tE; t++) {
                float w = alphas[t];
                float4 h = H0[(size_t)t * 128 + tid];
                acc.x += w * h.x; acc.y += w * h.y;
                acc.z += w * h.z; acc.w += w * h.w;
            }
            // closing fire step: cur = dist_completion
            float4 h = H0[(size_t)tE * 128 + tid];
            acc.x += wE * h.x; acc.y += wE * h.y;
            acc.z += wE * h.z; acc.w += wE * h.w;
            *orow = acc;
        }
    } else {
        // frame_new for batch b: tail segment after last fire
        int b = i - TT;
        const float4* Hb = (const float4*)(hidden + (size_t)b * TT * HH);
        int lf = g_lastFire[b];
        float4 acc;
        int tstart;
        if (lf < 0) {
            acc = ((const float4*)frame)[(size_t)b * 128 + tid];
            tstart = 0;
        } else {
            float dist = g_lastDist[b];
            float rem = alphas[(size_t)b * TT + lf] - dist;
            float4 h = Hb[(size_t)lf * 128 + tid];
            acc.x = rem * h.x; acc.y = rem * h.y;
            acc.z = rem * h.z; acc.w = rem * h.w;
            tstart = lf + 1;
        }
        for (int t = tstart; t < TT; t++) {
            float w = alphas[(size_t)b * TT + t];
            float4 h = Hb[(size_t)t * 128 + tid];
            acc.x += w * h.x; acc.y += w * h.y;
            acc.z += w * h.z; acc.w += w * h.w;
        }
        // out layout: [frame_sel T*H][integrate_new B][frame_new B*H]
        float4* od = (float4*)(out + (size_t)TT * HH + BB) + (size_t)b * 128 + tid;
        *od = acc;
    }
}

extern "C" void kernel_launch(void* const* d_in, const int* in_sizes, int n_in,
                              void* d_out, int out_size) {
    const float* hidden    = (const float*)d_in[0];
    const float* alphas    = (const float*)d_in[1];
    const float* integrate = (const float*)d_in[2];
    const float* frame     = (const float*)d_in[3];
    float* out = (float*)d_out;

    k_scan<<<1, 32>>>(alphas, integrate, out + (size_t)TT * HH);
    k_frames<<<TT + BB, 128>>>(hidden, alphas, integrate, frame, out);
}

// round 7
// speedup vs baseline: 1.0413x; 1.0413x over previous
#include <cuda_runtime.h>

#define TT 2048
#define BB 32
#define HH 512

// Scratch (allocation-free: __device__ globals)
__device__ uint2 g_fire[TT];       // (t, bits(dist_completion)) per batch-0 fire
__device__ int   g_nF;             // number of fires, batch 0
__device__ int   g_lastFire[BB];   // last fire index per batch (-1 if none)
__device__ float g_lastDist[BB];   // dist_completion at that fire

// Carry reconstruction: x-1 exact for x in [1,2) (Sterbenz)
__device__ __forceinline__ float integ_after(float x) {
    return (x >= 1.0f) ? (x - 1.0f) : x;
}

// ---------------------------------------------------------------------------
// Kernel 1: single-warp scan, lane = batch. Bit-exact f32 sequential.
// Chain per step (NO predicates, NO branches):
//   z=x-1 (FADD, exact) -> xb=z+a (FADD) / m=sign(z) (SHF) -> LOP3 bitsel
//   = 12 cycles. xa=x+a runs in parallel.
// Uniform step: x_t = STEP(x_{t-1}, a_t), with x_{-1}=integ0 (resolution is
// identity since integ0<1). Final integ = STEP(x_{TT-1}, 0).
// Per-lane last-fire bookkeeping is recovered post-loop from a 128-deep
// shared ring of x values (fire gaps >127 have probability ~1/127!).
// Batch-0 fire list is compacted post-loop from full x history via ballot.
// ---------------------------------------------------------------------------
__global__ void k_scan(const float* __restrict__ alphas,
                       const float* __restrict__ integrate,
                       float* __restrict__ out_integ) {
    __shared__ float s_x[TT];              // lane-0 full x history
    __shared__ float s_dummy[64];          // write sink for lanes 1..31
    __shared__ float s_ring[128 * 32];     // last-128 x per lane: [t&127][lane]
    int lane = threadIdx.x;
    const float4* A = (const float4*)(alphas + lane * TT);  // lane's batch row
    float integ0 = integrate[lane];
    float x = integ0;                      // x_{-1}

    float4 buf[8], nxt[8];
#pragma unroll
    for (int j = 0; j < 8; j++) buf[j] = A[j];

#define GETA(B, u) ((u & 3) == 0 ? B[(u) >> 2].x : \
                    (u & 3) == 1 ? B[(u) >> 2].y : \
                    (u & 3) == 2 ? B[(u) >> 2].z : B[(u) >> 2].w)

    // spt/rpt: immediate-offset STS bases, recomputed per 32-step window.
#define BODY32(B, TBASE) do {                                         \
    float* spt = ((lane == 0) ? s_x + (TBASE) : s_dummy);             \
    float* rpt = s_ring + (((TBASE) & 127) * 32 + lane);              \
    _Pragma("unroll")                                                 \
    for (int u = 0; u < 32; u++) {                                    \
        float a  = GETA(B, u);                                        \
        float z  = x - 1.0f;         /* exact (Sterbenz)           */ \
        float xa = x + a;            /* no-fire continuation        */ \
        float xb = z + a;            /* fired continuation (fine rnd)*/ \
        int   m  = __float_as_int(z) >> 31;  /* FFFF.. = no fire    */ \
        x = __int_as_float((__float_as_int(xb) & ~m) |                \
                           (__float_as_int(xa) &  m));                \
        spt[(lane == 0) ? u : (u & 31)] = x;  /* lane0 history      */ \
        rpt[u * 32] = x;                      /* ring, all lanes    */ \
    } } while (0)

    for (int b2 = 0; b2 < TT / 64; b2++) {
#pragma unroll
        for (int j = 0; j < 8; j++) nxt[j] = A[b2 * 16 + 8 + j];
        BODY32(buf, b2 * 64);
        if (b2 + 1 < TT / 64) {
#pragma unroll
            for (int j = 0; j < 8; j++) buf[j] = A[(b2 + 1) * 16 + j];
        }
        BODY32(nxt, b2 * 64 + 32);
    }

    // Final resolution: STEP with a = 0 (x+0 and z+0 are exact).
    {
        float z = x - 1.0f;
        int   m = __float_as_int(z) >> 31;
        x = __int_as_float((__float_as_int(z) & ~m) | (__float_as_int(x) & m));
    }
    out_integ[lane] = x;                   // integrate_new output

    __syncwarp();

    // Per-lane last fire from the ring (backward scan, ~2-4 iters typical)
    {
        int lf = -1; float dist = 0.0f;
        for (int k = 1; k <= 127; k++) {
            int t = TT - k;
            float xt = s_ring[(t & 127) * 32 + lane];
            if (xt >= 1.0f) {
                float xp = s_ring[((t - 1) & 127) * 32 + lane];
                dist = 1.0f - integ_after(xp);   // 1 - integ_pre at fire
                lf = t;
                break;
            }
        }
        g_lastFire[lane] = lf;
        g_lastDist[lane] = dist;
    }

    // Ballot-based compaction of batch-0 fires (64 iterations)
    float i0 = __shfl_sync(0xffffffffu, integ0, 0);
    int cnt = 0;
    for (int base = 0; base < TT; base += 32) {
        float xv = s_x[base + lane];
        bool  f = (xv >= 1.0f);
        unsigned msk = __ballot_sync(0xffffffffu, f);
        if (f) {
            int pos = cnt + __popc(msk & ((1u << lane) - 1u));
            float xprev = (base + lane == 0) ? i0 : integ_after(s_x[base + lane - 1]);
            float dist  = 1.0f - xprev;           // dist_completion at this fire
            g_fire[pos] = make_uint2((unsigned)(base + lane), __float_as_uint(dist));
        }
        cnt += __popc(msk);
    }
    if (lane == 0) g_nF = cnt;
}

// ---------------------------------------------------------------------------
// Kernel 2: blocks 0..2047 -> frame_sel rows; blocks 2048..2079 -> frame_new.
// 128 threads, float4 over H=512. Interior loops unrolled x4 with clamped
// predicated loads (w=0 padding is exact) to raise MLP on DRAM latency.
// ---------------------------------------------------------------------------
__global__ void k_frames(const float* __restrict__ hidden,
                         const float* __restrict__ alphas,
                         const float* __restrict__ integrate,
                         const float* __restrict__ frame,
                         float* __restrict__ out) {
    int i   = blockIdx.x;
    int tid = threadIdx.x;  // 0..127

    if (i < TT) {
        const float4* H0 = (const float4*)hidden;  // batch 0: [t][128]
        float4* orow = (float4*)out + (size_t)i * 128 + tid;
        int nF = g_nF;

        if (i >= nF) {
            // fill rows replicate frames[0][0] = frame_init + cur_0 * h_0
            float cur0;
            if (nF > 0 && g_fire[0].x == 0u)
                cur0 = __uint_as_float(g_fire[0].y);   // fired at t=0: dist
            else
                cur0 = alphas[0];                      // no fire at t=0: alpha
            float4 h = H0[tid];
            float4 f = ((const float4*)frame)[tid];
            float4 r;
            r.x = f.x + cur0 * h.x; r.y = f.y + cur0 * h.y;
            r.z = f.z + cur0 * h.z; r.w = f.w + cur0 * h.w;
            *orow = r;
        } else {
            uint2 fe = g_fire[i];
            int   tE = (int)fe.x;
            float wE = __uint_as_float(fe.y);          // cur at closing fire
            float4 acc;
            int tstart;
            if (i == 0) {
                acc = ((const float4*)frame)[tid];     // initial frame carried in
                tstart = 0;
            } else {
                // lead term from previous fire: rem_{tp} * h_{tp}
                uint2 fp = g_fire[i - 1];
                int   tp = (int)fp.x;
                float cur_p = __uint_as_float(fp.y);
                float rem = alphas[tp] - cur_p;        // bitwise same as scan's rem
                float4 h = H0[(size_t)tp * 128 + tid];
                acc.x = rem * h.x; acc.y = rem * h.y;
                acc.z = rem * h.z; acc.w = rem * h.w;
                tstart = tp + 1;
            }
            // interior steps (non-fire): cur = alpha. x4 unroll, MLP=4.
            for (int t = tstart; t < tE; t += 4) {
#pragma unroll
                for (int k = 0; k < 4; k++) {
                    int tt = t + k;
                    int ti = (tt < tE) ? tt : (tE - 1);
                    float w = (tt < tE) ? alphas[ti] : 0.0f;
                    float4 h = H0[(size_t)ti * 128 + tid];
                    acc.x += w * h.x; acc.y += w * h.y;
                    acc.z += w * h.z; acc.w += w * h.w;
                }
            }
            // closing fire step: cur = dist_completion
            float4 h = H0[(size_t)tE * 128 + tid];
            acc.x += wE * h.x; acc.y += wE * h.y;
            acc.z += wE * h.z; acc.w += wE * h.w;
            *orow = acc;
        }
    } else {
        // frame_new for batch b: tail segment after last fire
        int b = i - TT;
        const float4* Hb = (const float4*)(hidden + (size_t)b * TT * HH);
        int lf = g_lastFire[b];
        float4 acc;
        int tstart;
        if (lf < 0) {
            acc = ((const float4*)frame)[(size_t)b * 128 + tid];
            tstart = 0;
        } else {
            float dist = g_lastDist[b];
            float rem = alphas[(size_t)b * TT + lf] - dist;
            float4 h = Hb[(size_t)lf * 128 + tid];
            acc.x = rem * h.x; acc.y = rem * h.y;
            acc.z = rem * h.z; acc.w = rem * h.w;
            tstart = lf + 1;
        }
        for (int t = tstart; t < TT; t += 4) {
#pragma unroll
            for (int k = 0; k < 4; k++) {
                int tt = t + k;
                int ti = (tt < TT) ? tt : (TT - 1);
                float w = (tt < TT) ? alphas[(size_t)b * TT + ti] : 0.0f;
                float4 h = Hb[(size_t)ti * 128 + tid];
                acc.x += w * h.x; acc.y += w * h.y;
                acc.z += w * h.z; acc.w += w * h.w;
            }
        }
        // out layout: [frame_sel T*H][integrate_new B][frame_new B*H]
        float4* od = (float4*)(out + (size_t)TT * HH + BB) + (size_t)b * 128 + tid;
        *od = acc;
    }
}

extern "C" void kernel_launch(void* const* d_in, const int* in_sizes, int n_in,
                              void* d_out, int out_size) {
    const float* hidden    = (const float*)d_in[0];
    const float* alphas    = (const float*)d_in[1];
    const float* integrate = (const float*)d_in[2];
    const float* frame     = (const float*)d_in[3];
    float* out = (float*)d_out;

    k_scan<<<1, 32>>>(alphas, integrate, out + (size_t)TT * HH);
    k_frames<<<TT + BB, 128>>>(hidden, alphas, integrate, frame, out);
}

// round 9
// speedup vs baseline: 1.3929x; 1.3377x over previous
#include <cuda_runtime.h>

#define TT 2048
#define BB 32
#define HH 512

// Scratch (allocation-free: __device__ globals)
__device__ uint2 g_fire[TT];       // (t, bits(dist_completion)) per batch-0 fire
__device__ int   g_nF;             // number of fires, batch 0
__device__ int   g_lastFire[BB];   // last fire index per batch (-1 if none)
__device__ float g_lastDist[BB];   // dist_completion at that fire

// Carry reconstruction: x-1 exact for x in [1,2) (Sterbenz)
__device__ __forceinline__ float integ_after(float x) {
    return (x >= 1.0f) ? (x - 1.0f) : x;
}

// ---------------------------------------------------------------------------
// Kernel 1: single-warp scan, lane = batch. Bit-exact f32 sequential.
// Chain/step: FADD(x=integ+a) -> FSETP(x>=1) -> FSEL = 4+4+4 = 12 cyc.
// The ternary `p ? y : x` is forced through selp.f32 so ptxas emits FSEL
// (predicate consumed as DATA, 4 cyc) instead of a guarded @P MOV
// (predicate as GUARD, 13 cyc — this was R4's 21-cyc/step chain).
// lf/lip selects share the same predicate inside the asm block, off-chain.
// Lane 0 records x_t to shared unconditionally; other lanes write a dummy
// region. Fire compaction happens once at the end via ballot.
// ---------------------------------------------------------------------------
__global__ void k_scan(const float* __restrict__ alphas,
                       const float* __restrict__ integrate,
                       float* __restrict__ out_integ) {
    __shared__ float s_x[TT];
    __shared__ float s_dummy[TT + 2];
    int lane = threadIdx.x;
    const float4* A = (const float4*)(alphas + lane * TT);  // lane's batch row
    float integ0 = integrate[lane];
    float integ  = integ0;
    int   lf  = -1;                       // last fire index
    float lip = 0.0f;                     // integ entering last fire step
    float* sp = (lane == 0) ? s_x : (s_dummy + 1);

    float4 buf[8], nxt[8];
#pragma unroll
    for (int j = 0; j < 8; j++) buf[j] = A[j];

#define GETA(B, u) ((u & 3) == 0 ? B[(u) >> 2].x : \
                    (u & 3) == 1 ? B[(u) >> 2].y : \
                    (u & 3) == 2 ? B[(u) >> 2].z : B[(u) >> 2].w)

#define BODY32(B, TBASE) do {                                        \
    float* spt = sp + (TBASE);                                       \
    _Pragma("unroll")                                                \
    for (int u = 0; u < 32; u++) {                                   \
        float a = GETA(B, u);                                        \
        float x = integ + a;          /* FADD: fl(integ+alpha)    */ \
        float y = x - 1.0f;           /* FADD: exact on [1,2)     */ \
        spt[u] = x;                   /* STS [R+imm], branchless  */ \
        float iold = integ;                                          \
        int   t = (TBASE) + u;                                       \
        float newi;                                                  \
        asm("{\n\t"                                                  \
            ".reg .pred p;\n\t"                                      \
            "setp.ge.f32 p, %3, 0f3F800000;\n\t"                     \
            "selp.f32 %0, %4, %3, p;\n\t"  /* integ' = p?y:x  */     \
            "selp.b32 %1, %5, %1, p;\n\t"  /* lf = p?t:lf     */     \
            "selp.f32 %2, %6, %2, p;\n\t"  /* lip = p?iold:lip */    \
            "}"                                                      \
            : "=f"(newi), "+r"(lf), "+f"(lip)                        \
            : "f"(x), "f"(y), "r"(t), "f"(iold));                    \
        integ = newi;                                                \
    } } while (0)

    for (int b2 = 0; b2 < TT / 64; b2++) {
#pragma unroll
        for (int j = 0; j < 8; j++) nxt[j] = A[b2 * 16 + 8 + j];
        BODY32(buf, b2 * 64);
        if (b2 + 1 < TT / 64) {
#pragma unroll
            for (int j = 0; j < 8; j++) buf[j] = A[(b2 + 1) * 16 + j];
        }
        BODY32(nxt, b2 * 64 + 32);
    }

    g_lastFire[lane] = lf;
    g_lastDist[lane] = 1.0f - lip;      // fl(1 - integ_pre) at last fire
    out_integ[lane]  = integ;           // integrate_new output

    __syncwarp();
    // Ballot-based compaction of batch-0 fires (64 iterations)
    float i0 = __shfl_sync(0xffffffffu, integ0, 0);
    int cnt = 0;
    for (int base = 0; base < TT; base += 32) {
        float xv = s_x[base + lane];
        bool  f = (xv >= 1.0f);
        unsigned msk = __ballot_sync(0xffffffffu, f);
        if (f) {
            int pos = cnt + __popc(msk & ((1u << lane) - 1u));
            float xprev = (base + lane == 0) ? i0 : integ_after(s_x[base + lane - 1]);
            float dist  = 1.0f - xprev;           // dist_completion at this fire
            g_fire[pos] = make_uint2((unsigned)(base + lane), __float_as_uint(dist));
        }
        cnt += __popc(msk);
    }
    if (lane == 0) g_nF = cnt;
}

// ---------------------------------------------------------------------------
// Kernel 2: blocks 0..2047 -> frame_sel rows; blocks 2048..2079 -> frame_new.
// 128 threads, float4 over H=512. Interior loops unrolled x4 with clamped
// predicated loads (w=0 padding is exact) to raise MLP on DRAM latency.
// ---------------------------------------------------------------------------
__global__ void k_frames(const float* __restrict__ hidden,
                         const float* __restrict__ alphas,
                         const float* __restrict__ integrate,
                         const float* __restrict__ frame,
                         float* __restrict__ out) {
    int i   = blockIdx.x;
    int tid = threadIdx.x;  // 0..127

    if (i < TT) {
        const float4* H0 = (const float4*)hidden;  // batch 0: [t][128]
        float4* orow = (float4*)out + (size_t)i * 128 + tid;
        int nF = g_nF;

        if (i >= nF) {
            // fill rows replicate frames[0][0] = frame_init + cur_0 * h_0
            float cur0;
            if (nF > 0 && g_fire[0].x == 0u)
                cur0 = __uint_as_float(g_fire[0].y);   // fired at t=0: dist
            else
                cur0 = alphas[0];                      // no fire at t=0: alpha
            float4 h = H0[tid];
            float4 f = ((const float4*)frame)[tid];
            float4 r;
            r.x = f.x + cur0 * h.x; r.y = f.y + cur0 * h.y;
            r.z = f.z + cur0 * h.z; r.w = f.w + cur0 * h.w;
            *orow = r;
        } else {
            uint2 fe = g_fire[i];
            int   tE = (int)fe.x;
            float wE = __uint_as_float(fe.y);          // cur at closing fire
            float4 acc;
            int tstart;
            if (i == 0) {
                acc = ((const float4*)frame)[tid];     // initial frame carried in
                tstart = 0;
            } else {
                // lead term from previous fire: rem_{tp} * h_{tp}
                uint2 fp = g_fire[i - 1];
                int   tp = (int)fp.x;
                float cur_p = __uint_as_float(fp.y);
                float rem = alphas[tp] - cur_p;        // bitwise same as scan's rem
                float4 h = H0[(size_t)tp * 128 + tid];
                acc.x = rem * h.x; acc.y = rem * h.y;
                acc.z = rem * h.z; acc.w = rem * h.w;
                tstart = tp + 1;
            }
            // interior steps (non-fire): cur = alpha. x4 unroll, MLP=4.
            for (int t = tstart; t < tE; t += 4) {
#pragma unroll
                for (int k = 0; k < 4; k++) {
                    int tt = t + k;
                    int ti = (tt < tE) ? tt : (tE - 1);
                    float w = (tt < tE) ? alphas[ti] : 0.0f;
                    float4 h = H0[(size_t)ti * 128 + tid];
                    acc.x += w * h.x; acc.y += w * h.y;
                    acc.z += w * h.z; acc.w += w * h.w;
                }
            }
            // closing fire step: cur = dist_completion
            float4 h = H0[(size_t)tE * 128 + tid];
            acc.x += wE * h.x; acc.y += wE * h.y;
            acc.z += wE * h.z; acc.w += wE * h.w;
            *orow = acc;
        }
    } else {
        // frame_new for batch b: tail segment after last fire
        int b = i - TT;
        const float4* Hb = (const float4*)(hidden + (size_t)b * TT * HH);
        int lf = g_lastFire[b];
        float4 acc;
        int tstart;
        if (lf < 0) {
            acc = ((const float4*)frame)[(size_t)b * 128 + tid];
            tstart = 0;
        } else {
            float dist = g_lastDist[b];
            float rem = alphas[(size_t)b * TT + lf] - dist;
            float4 h = Hb[(size_t)lf * 128 + tid];
            acc.x = rem * h.x; acc.y = rem * h.y;
            acc.z = rem * h.z; acc.w = rem * h.w;
            tstart = lf + 1;
        }
        for (int t = tstart; t < TT; t += 4) {
#pragma unroll
            for (int k = 0; k < 4; k++) {
                int tt = t + k;
                int ti = (tt < TT) ? tt : (TT - 1);
                float w = (tt < TT) ? alphas[(size_t)b * TT + ti] : 0.0f;
                float4 h = Hb[(size_t)ti * 128 + tid];
                acc.x += w * h.x; acc.y += w * h.y;
                acc.z += w * h.z; acc.w += w * h.w;
            }
        }
        // out layout: [frame_sel T*H][integrate_new B][frame_new B*H]
        float4* od = (float4*)(out + (size_t)TT * HH + BB) + (size_t)b * 128 + tid;
        *od = acc;
    }
}

extern "C" void kernel_launch(void* const* d_in, const int* in_sizes, int n_in,
                              void* d_out, int out_size) {
    const float* hidden    = (const float*)d_in[0];
    const float* alphas    = (const float*)d_in[1];
    const float* integrate = (const float*)d_in[2];
    const float* frame     = (const float*)d_in[3];
    float* out = (float*)d_out;

    k_scan<<<1, 32>>>(alphas, integrate, out + (size_t)TT * HH);
    k_frames<<<TT + BB, 128>>>(hidden, alphas, integrate, frame, out);
}

// round 10
// speedup vs baseline: 1.4744x; 1.0585x over previous
#include <cuda_runtime.h>

#define TT 2048
#define BB 32
#define HH 512

#define WPG   4            // windows (32 steps each) per group
#define GSTEPS (WPG * 32)  // 128 steps per group
#define NG    (TT / GSTEPS)

// Scratch (allocation-free: __device__ globals)
__device__ uint2 g_fire[TT];       // (t, bits(dist_completion)) per batch-0 fire
__device__ int   g_nF;             // number of fires, batch 0
__device__ int   g_lastFire[BB];   // last fire index per batch (-1 if none)
__device__ float g_lastDist[BB];   // dist_completion at that fire

// Carry reconstruction: x-1 exact for x in [1,2) (Sterbenz)
__device__ __forceinline__ float integ_after(float x) {
    return (x >= 1.0f) ? (x - 1.0f) : x;
}

// ---------------------------------------------------------------------------
// Kernel 1: warp-specialized scan. Warp 0 = consumer (sequential CIF scan,
// lane = batch, bit-exact f32); warps 1..4 = producers that stage alphas
// into smem, transposed [t][b] with stride 33 (conflict-free), using
// COALESCED LDG.128 (4 lines/load instead of 32 — the R4/R9 scans were
// L1tex-wavefront-bound on stride-8KB lane loads: 8 LDG x 32 wf x ~2 cyc
// ~ 530 cyc per 32-step window vs 384-cyc chain budget).
// Chain/step: FADD -> FSETP -> FSEL (selp-as-data) = 12 cyc.
// ---------------------------------------------------------------------------
__global__ void __launch_bounds__(160, 1)
k_scan(const float* __restrict__ alphas,
       const float* __restrict__ integrate,
       float* __restrict__ out_integ) {
    __shared__ float s_x[TT];               // lane-0 x history
    __shared__ float s_dummy[64];           // write sink for lanes 1..31
    __shared__ float s_a[2][WPG][32 * 33];  // staged alpha tiles, [t][b] pad 33
    int tid  = threadIdx.x;
    int wid  = tid >> 5;
    int lane = tid & 31;

    // ---- producer: warp w stages window (g*WPG + w-1) into s_a[g&1][w-1]
    auto produce = [&](int g) {
        if (wid >= 1) {
            int tb = (g * WPG + (wid - 1)) * 32;
            float* tile = s_a[g & 1][wid - 1];
            int m  = lane & 7;        // t-quad within row
            int r0 = lane >> 3;       // row (batch) offset
#pragma unroll
            for (int c = 0; c < 8; c++) {
                int b = c * 4 + r0;   // batch 0..31
                float4 v = *(const float4*)(alphas + b * TT + tb + 4 * m);
                tile[(4 * m + 0) * 33 + b] = v.x;
                tile[(4 * m + 1) * 33 + b] = v.y;
                tile[(4 * m + 2) * 33 + b] = v.z;
                tile[(4 * m + 3) * 33 + b] = v.w;
            }
        }
    };

    float integ0 = 0.0f, integ = 0.0f, lip = 0.0f;
    int lf = -1;
    if (wid == 0) {
        integ0 = integrate[lane];
        integ  = integ0;
    }

    produce(0);
    __syncthreads();

    for (int g = 0; g < NG; g++) {
        if (g + 1 < NG) produce(g + 1);
        if (wid == 0) {
#pragma unroll
            for (int wi = 0; wi < WPG; wi++) {
                const float* tile = s_a[g & 1][wi];
                float av[32];
#pragma unroll
                for (int u = 0; u < 32; u++) av[u] = tile[u * 33 + lane];
                int TB = g * GSTEPS + wi * 32;
                float* spt = (lane == 0) ? (s_x + TB) : s_dummy;
#pragma unroll
                for (int u = 0; u < 32; u++) {
                    float a = av[u];
                    float x = integ + a;      // FADD: fl(integ+alpha)
                    float y = x - 1.0f;       // FADD: exact on [1,2)
                    spt[u] = x;               // STS [R+imm], branchless
                    float iold = integ;
                    int   t = TB + u;
                    float newi;
                    asm("{\n\t"
                        ".reg .pred p;\n\t"
                        "setp.ge.f32 p, %3, 0f3F800000;\n\t"
                        "selp.f32 %0, %4, %3, p;\n\t"   /* integ' = p?y:x   */
                        "selp.b32 %1, %5, %1, p;\n\t"   /* lf    = p?t:lf   */
                        "selp.f32 %2, %6, %2, p;\n\t"   /* lip   = p?iold   */
                        "}"
                        : "=f"(newi), "+r"(lf), "+f"(lip)
                        : "f"(x), "f"(y), "r"(t), "f"(iold));
                    integ = newi;
                }
            }
        }
        __syncthreads();
    }

    if (wid != 0) return;

    g_lastFire[lane] = lf;
    g_lastDist[lane] = 1.0f - lip;      // fl(1 - integ_pre) at last fire
    out_integ[lane]  = integ;           // integrate_new output

    __syncwarp();
    // Ballot-based compaction of batch-0 fires (64 iterations)
    float i0 = __shfl_sync(0xffffffffu, integ0, 0);
    int cnt = 0;
    for (int base = 0; base < TT; base += 32) {
        float xv = s_x[base + lane];
        bool  f = (xv >= 1.0f);
        unsigned msk = __ballot_sync(0xffffffffu, f);
        if (f) {
            int pos = cnt + __popc(msk & ((1u << lane) - 1u));
            float xprev = (base + lane == 0) ? i0 : integ_after(s_x[base + lane - 1]);
            float dist  = 1.0f - xprev;           // dist_completion at this fire
            g_fire[pos] = make_uint2((unsigned)(base + lane), __float_as_uint(dist));
        }
        cnt += __popc(msk);
    }
    if (lane == 0) g_nF = cnt;
}

// ---------------------------------------------------------------------------
// Kernel 2: blocks 0..2047 -> frame_sel rows; blocks 2048..2079 -> frame_new.
// 128 threads, float4 over H=512. Interior loops unrolled x4 with clamped
// predicated loads (w=0 padding is exact) to raise MLP on DRAM latency.
// ---------------------------------------------------------------------------
__global__ void k_frames(const float* __restrict__ hidden,
                         const float* __restrict__ alphas,
                         const float* __restrict__ integrate,
                         const float* __restrict__ frame,
                         float* __restrict__ out) {
    int i   = blockIdx.x;
    int tid = threadIdx.x;  // 0..127

    if (i < TT) {
        const float4* H0 = (const float4*)hidden;  // batch 0: [t][128]
        float4* orow = (float4*)out + (size_t)i * 128 + tid;
        int nF = g_nF;

        if (i >= nF) {
            // fill rows replicate frames[0][0] = frame_init + cur_0 * h_0
            float cur0;
            if (nF > 0 && g_fire[0].x == 0u)
                cur0 = __uint_as_float(g_fire[0].y);   // fired at t=0: dist
            else
                cur0 = alphas[0];                      // no fire at t=0: alpha
            float4 h = H0[tid];
            float4 f = ((const float4*)frame)[tid];
            float4 r;
            r.x = f.x + cur0 * h.x; r.y = f.y + cur0 * h.y;
            r.z = f.z + cur0 * h.z; r.w = f.w + cur0 * h.w;
            *orow = r;
        } else {
            uint2 fe = g_fire[i];
            int   tE = (int)fe.x;
            float wE = __uint_as_float(fe.y);          // cur at closing fire
            float4 acc;
            int tstart;
            if (i == 0) {
                acc = ((const float4*)frame)[tid];     // initial frame carried in
                tstart = 0;
            } else {
                // lead term from previous fire: rem_{tp} * h_{tp}
                uint2 fp = g_fire[i - 1];
                int   tp = (int)fp.x;
                float cur_p = __uint_as_float(fp.y);
                float rem = alphas[tp] - cur_p;        // bitwise same as scan's rem
                float4 h = H0[(size_t)tp * 128 + tid];
                acc.x = rem * h.x; acc.y = rem * h.y;
                acc.z = rem * h.z; acc.w = rem * h.w;
                tstart = tp + 1;
            }
            // interior steps (non-fire): cur = alpha. x4 unroll, MLP=4.
            for (int t = tstart; t < tE; t += 4) {
#pragma unroll
                for (int k = 0; k < 4; k++) {
                    int tt = t + k;
                    int ti = (tt < tE) ? tt : (tE - 1);
                    float w = (tt < tE) ? alphas[ti] : 0.0f;
                    float4 h = H0[(size_t)ti * 128 + tid];
                    acc.x += w * h.x; acc.y += w * h.y;
                    acc.z += w * h.z; acc.w += w * h.w;
                }
            }
            // closing fire step: cur = dist_completion
            float4 h = H0[(size_t)tE * 128 + tid];
            acc.x += wE * h.x; acc.y += wE * h.y;
            acc.z += wE * h.z; acc.w += wE * h.w;
            *orow = acc;
        }
    } else {
        // frame_new for batch b: tail segment after last fire
        int b = i - TT;
        const float4* Hb = (const float4*)(hidden + (size_t)b * TT * HH);
        int lf = g_lastFire[b];
        float4 acc;
        int tstart;
        if (lf < 0) {
            acc = ((const float4*)frame)[(size_t)b * 128 + tid];
            tstart = 0;
        } else {
            float dist = g_lastDist[b];
            float rem = alphas[(size_t)b * TT + lf] - dist;
            float4 h = Hb[(size_t)lf * 128 + tid];
            acc.x = rem * h.x; acc.y = rem * h.y;
            acc.z = rem * h.z; acc.w = rem * h.w;
            tstart = lf + 1;
        }
        for (int t = tstart; t < TT; t += 4) {
#pragma unroll
            for (int k = 0; k < 4; k++) {
                int tt = t + k;
                int ti = (tt < TT) ? tt : (TT - 1);
                float w = (tt < TT) ? alphas[(size_t)b * TT + ti] : 0.0f;
                float4 h = Hb[(size_t)ti * 128 + tid];
                acc.x += w * h.x; acc.y += w * h.y;
                acc.z += w * h.z; acc.w += w * h.w;
            }
        }
        // out layout: [frame_sel T*H][integrate_new B][frame_new B*H]
        float4* od = (float4*)(out + (size_t)TT * HH + BB) + (size_t)b * 128 + tid;
        *od = acc;
    }
}

extern "C" void kernel_launch(void* const* d_in, const int* in_sizes, int n_in,
                              void* d_out, int out_size) {
    const float* hidden    = (const float*)d_in[0];
    const float* alphas    = (const float*)d_in[1];
    const float* integrate = (const float*)d_in[2];
    const float* frame     = (const float*)d_in[3];
    float* out = (float*)d_out;

    k_scan<<<1, 160>>>(alphas, integrate, out + (size_t)TT * HH);
    k_frames<<<TT + BB, 128>>>(hidden, alphas, integrate, frame, out);
}

// round 12
// speedup vs baseline: 1.7469x; 1.1848x over previous
#include <cuda_runtime.h>

#define TT 2048
#define BB 32
#define HH 512

#define WPG   4            // windows (32 steps each) per group
#define GSTEPS (WPG * 32)  // 128 steps per group
#define NG    (TT / GSTEPS)

// Scratch (allocation-free: __device__ globals)
__device__ uint2 g_fire[TT];       // (t, bits(dist_completion)) per batch-0 fire
__device__ int   g_nF;             // number of fires, batch 0
__device__ int   g_lastFire[BB];   // last fire index per batch (-1 if none)
__device__ float g_lastDist[BB];   // dist_completion at that fire

// Carry reconstruction: x-1 exact for x in [1,2) (Sterbenz)
__device__ __forceinline__ float integ_after(float x) {
    return (x >= 1.0f) ? (x - 1.0f) : x;
}

// ---------------------------------------------------------------------------
// Kernel 1: warp-specialized scan. Warp 0 = consumer (sequential CIF scan,
// lane = batch, bit-exact f32); warps 1..4 = producers staging alphas into
// smem transposed [t][b] (stride 33) with coalesced LDG.128.
//
// LAGGED-RESOLUTION chain (formulation B): carry is the UNRESOLVED x.
// Step t resolves fire(t-1) and adds a_t:
//   z=x-1, xa=x+a, xb=z+a (FADDs); p=[x>=1] (FSETP, starts at step BEGIN,
//   parallel with the adds); x'=p?xb:xa (FSEL).
// Even with ptxas's conservative 13-cyc FSETP->consumer budget the period is
// max(13, 8)+4 ~ 17 cyc/step vs 21 for the resolved-carry form where the
// compare sits AFTER the add on the chain. All float expressions are
// bitwise-identical to the reference recurrence.
// ---------------------------------------------------------------------------
__global__ void __launch_bounds__(160, 1)
k_scan(const float* __restrict__ alphas,
       const float* __restrict__ integrate,
       float* __restrict__ out_integ) {
    __shared__ float s_x[TT];               // lane-0 x history (unresolved x_t)
    __shared__ float s_dummy[64];           // write sink for lanes 1..31
    __shared__ float s_a[2][WPG][32 * 33];  // staged alpha tiles, [t][b] pad 33
    int tid  = threadIdx.x;
    int wid  = tid >> 5;
    int lane = tid & 31;

    // ---- producer: warp w stages window (g*WPG + w-1) into s_a[g&1][w-1]
    auto produce = [&](int g) {
        if (wid >= 1) {
            int tb = (g * WPG + (wid - 1)) * 32;
            float* tile = s_a[g & 1][wid - 1];
            int m  = lane & 7;        // t-quad within row
            int r0 = lane >> 3;       // row (batch) offset
#pragma unroll
            for (int c = 0; c < 8; c++) {
                int b = c * 4 + r0;   // batch 0..31
                float4 v = *(const float4*)(alphas + b * TT + tb + 4 * m);
                tile[(4 * m + 0) * 33 + b] = v.x;
                tile[(4 * m + 1) * 33 + b] = v.y;
                tile[(4 * m + 2) * 33 + b] = v.z;
                tile[(4 * m + 3) * 33 + b] = v.w;
            }
        }
    };

    float integ0 = 0.0f;
    float x  = 0.0f;                  // unresolved carry x_{t-1}; x_{-1}=integ0<1
    float ip = 0.0f;                  // resolved carry entering step t-1 (lag 1)
    float li = 0.0f;                  // resolved carry entering the last fire
    int   lf = -1;                    // last fire index
    if (wid == 0) {
        integ0 = integrate[lane];
        x = integ0;
    }

    produce(0);
    __syncthreads();

    for (int g = 0; g < NG; g++) {
        if (g + 1 < NG) produce(g + 1);
        if (wid == 0) {
#pragma unroll
            for (int wi = 0; wi < WPG; wi++) {
                const float* tile = s_a[g & 1][wi];
                float av[32];
#pragma unroll
                for (int u = 0; u < 32; u++) av[u] = tile[u * 33 + lane];
                int TB = g * GSTEPS + wi * 32;
                float* spt = (lane == 0) ? (s_x + TB) : s_dummy;
#pragma unroll
                for (int u = 0; u < 32; u++) {
                    float a  = av[u];
                    float z  = x - 1.0f;   // exact (Sterbenz) when fired
                    float xa = x + a;      // next x if no fire at t-1
                    float xb = z + a;      // next x if fired at t-1
                    int   tm1 = TB + u - 1;
                    float xn;
                    asm("{\n\t"
                        ".reg .pred p;\n\t"
                        "setp.ge.f32 p, %4, 0f3F800000;\n\t" /* fire(t-1)   */
                        "selp.f32 %2, %1, %2, p;\n\t"  /* li = p?ip:li     */
                        "selp.b32 %3, %7, %3, p;\n\t"  /* lf = p?(t-1):lf  */
                        "selp.f32 %1, %5, %4, p;\n\t"  /* ip = p?z:x       */
                        "selp.f32 %0, %6, %8, p;\n\t"  /* x' = p?xb:xa     */
                        "}"
                        : "=f"(xn), "+f"(ip), "+f"(li), "+r"(lf)
                        : "f"(x), "f"(z), "f"(xb), "r"(tm1), "f"(xa));
                    x = xn;
                    spt[u] = x;            // s_x[t] = unresolved x_t ("fires")
                }
            }
        }
        __syncthreads();
    }

    if (wid != 0) return;

    // Epilogue (runs once — plain C++, no perf weight): resolve pending fire
    // at t = TT-1 and finalize the carry. Same expressions, same bits.
    {
        bool fired = (x >= 1.0f);
        float z = x - 1.0f;            // exact when fired
        li = fired ? ip : li;
        lf = fired ? (TT - 1) : lf;
        x  = fired ? z : x;
    }
    g_lastFire[lane] = lf;
    g_lastDist[lane] = 1.0f - li;       // fl(1 - integ entering last fire)
    out_integ[lane]  = x;               // integrate_new output

    __syncwarp();
    // Ballot-based compaction of batch-0 fires (64 iterations)
    float i0 = __shfl_sync(0xffffffffu, integ0, 0);
    int cnt = 0;
    for (int base = 0; base < TT; base += 32) {
        float xv = s_x[base + lane];
        bool  f = (xv >= 1.0f);
        unsigned msk = __ballot_sync(0xffffffffu, f);
        if (f) {
            int pos = cnt + __popc(msk & ((1u << lane) - 1u));
            float xprev = (base + lane == 0) ? i0 : integ_after(s_x[base + lane - 1]);
            float dist  = 1.0f - xprev;           // dist_completion at this fire
            g_fire[pos] = make_uint2((unsigned)(base + lane), __float_as_uint(dist));
        }
        cnt += __popc(msk);
    }
    if (lane == 0) g_nF = cnt;
}

// ---------------------------------------------------------------------------
// Kernel 2: blocks 0..2047 -> frame_sel rows; blocks 2048..2079 -> frame_new.
// 128 threads, float4 over H=512. Interior loops unrolled x4 with clamped
// predicated loads (w=0 padding is exact) to raise MLP on DRAM latency.
// ---------------------------------------------------------------------------
__global__ void k_frames(const float* __restrict__ hidden,
                         const float* __restrict__ alphas,
                         const float* __restrict__ integrate,
                         const float* __restrict__ frame,
                         float* __restrict__ out) {
    int i   = blockIdx.x;
    int tid = threadIdx.x;  // 0..127

    if (i < TT) {
        const float4* H0 = (const float4*)hidden;  // batch 0: [t][128]
        float4* orow = (float4*)out + (size_t)i * 128 + tid;
        int nF = g_nF;

        if (i >= nF) {
            // fill rows replicate frames[0][0] = frame_init + cur_0 * h_0
            float cur0;
            if (nF > 0 && g_fire[0].x == 0u)
                cur0 = __uint_as_float(g_fire[0].y);   // fired at t=0: dist
            else
                cur0 = alphas[0];                      // no fire at t=0: alpha
            float4 h = H0[tid];
            float4 f = ((const float4*)frame)[tid];
            float4 r;
            r.x = f.x + cur0 * h.x; r.y = f.y + cur0 * h.y;
            r.z = f.z + cur0 * h.z; r.w = f.w + cur0 * h.w;
            *orow = r;
        } else {
            uint2 fe = g_fire[i];
            int   tE = (int)fe.x;
            float wE = __uint_as_float(fe.y);          // cur at closing fire
            float4 acc;
            int tstart;
            if (i == 0) {
                acc = ((const float4*)frame)[tid];     // initial frame carried in
                tstart = 0;
            } else {
                // lead term from previous fire: rem_{tp} * h_{tp}
                uint2 fp = g_fire[i - 1];
                int   tp = (int)fp.x;
                float cur_p = __uint_as_float(fp.y);
                float rem = alphas[tp] - cur_p;        // bitwise same as scan's rem
                float4 h = H0[(size_t)tp * 128 + tid];
                acc.x = rem * h.x; acc.y = rem * h.y;
                acc.z = rem * h.z; acc.w = rem * h.w;
                tstart = tp + 1;
            }
            // interior steps (non-fire): cur = alpha. x4 unroll, MLP=4.
            for (int t = tstart; t < tE; t += 4) {
#pragma unroll
                for (int k = 0; k < 4; k++) {
                    int tt = t + k;
                    int ti = (tt < tE) ? tt : (tE - 1);
                    float w = (tt < tE) ? alphas[ti] : 0.0f;
                    float4 h = H0[(size_t)ti * 128 + tid];
                    acc.x += w * h.x; acc.y += w * h.y;
                    acc.z += w * h.z; acc.w += w * h.w;
                }
            }
            // closing fire step: cur = dist_completion
            float4 h = H0[(size_t)tE * 128 + tid];
            acc.x += wE * h.x; acc.y += wE * h.y;
            acc.z += wE * h.z; acc.w += wE * h.w;
            *orow = acc;
        }
    } else {
        // frame_new for batch b: tail segment after last fire
        int b = i - TT;
        const float4* Hb = (const float4*)(hidden + (size_t)b * TT * HH);
        int lf = g_lastFire[b];
        float4 acc;
        int tstart;
        if (lf < 0) {
            acc = ((const float4*)frame)[(size_t)b * 128 + tid];
            tstart = 0;
        } else {
            float dist = g_lastDist[b];
            float rem = alphas[(size_t)b * TT + lf] - dist;
            float4 h = Hb[(size_t)lf * 128 + tid];
            acc.x = rem * h.x; acc.y = rem * h.y;
            acc.z = rem * h.z; acc.w = rem * h.w;
            tstart = lf + 1;
        }
        for (int t = tstart; t < TT; t += 4) {
#pragma unroll
            for (int k = 0; k < 4; k++) {
                int tt = t + k;
                int ti = (tt < TT) ? tt : (TT - 1);
                float w = (tt < TT) ? alphas[(size_t)b * TT + ti] : 0.0f;
                float4 h = Hb[(size_t)ti * 128 + tid];
                acc.x += w * h.x; acc.y += w * h.y;
                acc.z += w * h.z; acc.w += w * h.w;
            }
        }
        // out layout: [frame_sel T*H][integrate_new B][frame_new B*H]
        float4* od = (float4*)(out + (size_t)TT * HH + BB) + (size_t)b * 128 + tid;
        *od = acc;
    }
}

extern "C" void kernel_launch(void* const* d_in, const int* in_sizes, int n_in,
                              void* d_out, int out_size) {
    const float* hidden    = (const float*)d_in[0];
    const float* alphas    = (const float*)d_in[1];
    const float* integrate = (const float*)d_in[2];
    const float* frame     = (const float*)d_in[3];
    float* out = (float*)d_out;

    k_scan<<<1, 160>>>(alphas, integrate, out + (size_t)TT * HH);
    k_frames<<<TT + BB, 128>>>(hidden, alphas, integrate, frame, out);
}